// round 2
// baseline (speedup 1.0000x reference)
#include <cuda_runtime.h>
#include <math.h>

#define BB 64
#define CC 768
#define HH 64
#define WW 64
#define WFREQ 33            // W/2+1
#define PLANES (BB*CC)
#define WG_ELEMS (WFREQ*64) // 2112 per channel

// Pre-transposed gate: [c][k(0..32)][kh(0..63)]  (13.3 MB, static device mem)
__device__ float2 g_wgt[CC * WG_ELEMS];

// ---------------------------------------------------------------------------
// complex helpers
// ---------------------------------------------------------------------------
__device__ __forceinline__ float2 cadd(float2 a, float2 b){ return make_float2(a.x+b.x, a.y+b.y); }
__device__ __forceinline__ float2 csub(float2 a, float2 b){ return make_float2(a.x-b.x, a.y-b.y); }
__device__ __forceinline__ float2 cmul(float2 a, float2 b){
    return make_float2(fmaf(a.x,b.x,-a.y*b.y), fmaf(a.x,b.y, a.y*b.x));
}
// multiply by (0, DIR): DIR=-1 -> -i, DIR=+1 -> +i
template<int DIR>
__device__ __forceinline__ float2 muli(float2 a){
    return (DIR < 0) ? make_float2(a.y, -a.x) : make_float2(-a.y, a.x);
}

// ---------------------------------------------------------------------------
// 8-point complex FFT on registers, natural-order in AND out.
// DIR=-1: forward (e^{-i}), DIR=+1: inverse (e^{+i}), unnormalized.
// ---------------------------------------------------------------------------
template<int DIR>
__device__ __forceinline__ void fft8(float2 v[8]){
    const float s = 0.70710678118654752440f;
    float2 b0 = cadd(v[0], v[4]);
    float2 b1 = cadd(v[1], v[5]);
    float2 b2 = cadd(v[2], v[6]);
    float2 b3 = cadd(v[3], v[7]);
    float2 b4 = csub(v[0], v[4]);
    float2 b5 = csub(v[1], v[5]);
    float2 b6 = csub(v[2], v[6]);
    float2 b7 = csub(v[3], v[7]);
    b5 = cmul(b5, make_float2( s, DIR * s));   // W8^{±1}
    b6 = muli<DIR>(b6);                         // W8^{±2}
    b7 = cmul(b7, make_float2(-s, DIR * s));   // W8^{±3}
    float2 c0 = cadd(b0, b2), c2 = csub(b0, b2);
    float2 c1 = cadd(b1, b3), c3 = csub(b1, b3);
    c3 = muli<DIR>(c3);
    float2 c4 = cadd(b4, b6), c6 = csub(b4, b6);
    float2 c5 = cadd(b5, b7), c7 = csub(b5, b7);
    c7 = muli<DIR>(c7);
    float2 d0 = cadd(c0, c1), d1 = csub(c0, c1);
    float2 d2 = cadd(c2, c3), d3 = csub(c2, c3);
    float2 d4 = cadd(c4, c5), d5 = csub(c4, c5);
    float2 d6 = cadd(c6, c7), d7 = csub(c6, c7);
    // undo DIF bit-reversal
    v[0]=d0; v[1]=d4; v[2]=d2; v[3]=d6; v[4]=d1; v[5]=d5; v[6]=d3; v[7]=d7;
}

// ---------------------------------------------------------------------------
// 8x8 transpose across an aligned group of 8 lanes (each lane holds 8 complex).
// ---------------------------------------------------------------------------
__device__ __forceinline__ void transpose8(float2 v[8], unsigned mask, int lane8){
    #pragma unroll
    for (int m = 4; m >= 1; m >>= 1){
        bool up = (lane8 & m) != 0;
        #pragma unroll
        for (int i = 0; i < 8; i++){
            if ((i & m) == 0){
                int lo = i, hi = i | m;
                float2 t = up ? v[lo] : v[hi];
                t.x = __shfl_xor_sync(mask, t.x, m);
                t.y = __shfl_xor_sync(mask, t.y, m);
                if (up) v[lo] = t; else v[hi] = t;
            }
        }
    }
}

// ---------------------------------------------------------------------------
// 64-point FFT distributed over 8 lanes (four-step, radix 8x8).
// Forward (DIR=-1): input  v[n1] = x[8*n1 + j]   -> output v[k2] = X[j + 8*k2]
// Inverse (DIR=+1): input  v[n1] = C[8*n1 + j]   -> output v[k2] = y[j + 8*k2]
// twf[m] = e^{-2*pi*i * j*m / 64}
// ---------------------------------------------------------------------------
template<int DIR>
__device__ __forceinline__ void fft64(float2 v[8], const float2 twf[8],
                                      unsigned mask, int j){
    fft8<DIR>(v);
    #pragma unroll
    for (int m = 1; m < 8; m++){
        float2 w = twf[m];
        if (DIR > 0) w.y = -w.y;
        v[m] = cmul(v[m], w);
    }
    transpose8(v, mask, j);
    fft8<DIR>(v);
}

// ---------------------------------------------------------------------------
// prep: transpose complex_weight (H, WF, C, 2) -> g_wgt[c][k][kh]
// ---------------------------------------------------------------------------
__global__ void prep_weight_kernel(const float* __restrict__ w){
    int idx = blockIdx.x * blockDim.x + threadIdx.x;
    if (idx >= CC * WG_ELEMS) return;
    int c   = idx / WG_ELEMS;
    int rem = idx - c * WG_ELEMS;
    int k   = rem >> 6;     // 0..32
    int kh  = rem & 63;     // 0..63
    const float2* ws = (const float2*)w;  // float2 index = (kh*33 + k)*C + c
    g_wgt[idx] = ws[(kh * WFREQ + k) * CC + c];
}

// ---------------------------------------------------------------------------
// main kernel: one CTA per (b,c) plane. 256 threads = 32 groups of 8 lanes.
// ---------------------------------------------------------------------------
__global__ __launch_bounds__(256)
void sgn_kernel(const float* __restrict__ x, float* __restrict__ out){
    __shared__ __align__(16) float2 Bg[WFREQ][66];

    const int t    = threadIdx.x;
    const int j    = t & 7;        // lane within 8-group
    const int g    = t >> 3;       // group 0..31
    const int lane = t & 31;
    const unsigned mask = 0xFFu << (lane & 24);

    const int plane = blockIdx.x;              // = b*C + c
    const int c     = plane % CC;
    const float* xp = x   + (size_t)plane * (HH * WW);
    float*       op = out + (size_t)plane * (HH * WW);

    // per-lane twiddles: twf[m] = e^{-2*pi*i * j*m/64}
    float2 twf[8];
    #pragma unroll
    for (int m = 0; m < 8; m++){
        float sv, cv;
        sincospif((float)(j * m) * (1.0f / 32.0f), &sv, &cv);
        twf[m] = make_float2(cv, -sv);
    }

    // ---------------- forward row pass (pairs of rows packed) ---------------
    {
        float2 v[8];
        const int r2 = 2 * g;
        #pragma unroll
        for (int n1 = 0; n1 < 8; n1++){
            int w = 8 * n1 + j;
            v[n1].x = xp[r2 * 64 + w];
            v[n1].y = xp[(r2 + 1) * 64 + w];
        }
        fft64<-1>(v, twf, mask, j);     // v[k2] = Z_g[j + 8*k2]

        float2 got[8];
        const int mir = (8 - j) & 7;
        #pragma unroll
        for (int m = 0; m < 8; m++){
            got[m].x = __shfl_sync(mask, v[m].x, mir, 8);
            got[m].y = __shfl_sync(mask, v[m].y, mir, 8);
        }
        #pragma unroll
        for (int k2 = 0; k2 < 8; k2++){
            int k = j + 8 * k2;
            if (k <= 32){
                float2 Z  = v[k2];
                float2 Mv = (j == 0) ? got[(8 - k2) & 7] : got[7 - k2];
                float2 M  = make_float2(Mv.x, -Mv.y);          // conj(Z[64-k])
                float2 ge = make_float2(0.5f * (Z.x + M.x), 0.5f * (Z.y + M.y));
                float2 dd = make_float2(Z.x - M.x, Z.y - M.y);
                float2 go = make_float2(0.5f * dd.y, -0.5f * dd.x);  // -i/2 * d
                float4* p = (float4*)&Bg[k][r2];
                *p = make_float4(ge.x, ge.y, go.x, go.y);
            }
        }
    }
    __syncthreads();

    // ---- column pass: forward FFT -> gate -> inverse FFT, all in registers --
    const float2* wc_base = g_wgt + (size_t)c * WG_ELEMS;
    for (int it = 0; it < 2; it++){
        int q = g + 32 * it;          // frequency column k = q
        if (q < WFREQ){
            float2 u[8];
            #pragma unroll
            for (int n1 = 0; n1 < 8; n1++) u[n1] = Bg[q][8 * n1 + j];
            fft64<-1>(u, twf, mask, j);         // u[k2] = Xf[j+8*k2][q]
            const float2* wc = wc_base + q * 64;
            #pragma unroll
            for (int k2 = 0; k2 < 8; k2++) u[k2] = cmul(u[k2], wc[j + 8 * k2]);
            fft64<1>(u, twf, mask, j);          // u[n2] = g[j+8*n2][q]
            #pragma unroll
            for (int n2 = 0; n2 < 8; n2++) Bg[q][j + 8 * n2] = u[n2];
        }
    }
    __syncthreads();

    // ---------------- inverse row pass (pack two real rows) -----------------
    // c2r semantics: only the REAL parts of the DC (k=0) and Nyquist (k=32)
    // bins participate. Zeroing their imaginary parts makes C_a, C_b exactly
    // Hermitian, so IFFT(C_a), IFFT(C_b) are real and the two-rows-in-one-
    // complex-IFFT packing is exact (this was the Round-1 0.125 rel_err bug).
    {
        float2 v[8];
        const int r2 = 2 * g;
        #pragma unroll
        for (int n1 = 0; n1 < 8; n1++){
            int k = 8 * n1 + j;
            float2 a, b;
            if (k <= 32){
                float4 p = *(const float4*)&Bg[k][r2];
                a = make_float2(p.x,  p.y);
                b = make_float2(p.z,  p.w);
                if (k == 0 || k == 32){ a.y = 0.0f; b.y = 0.0f; }
            } else {
                float4 p = *(const float4*)&Bg[64 - k][r2];
                a = make_float2(p.x, -p.y);
                b = make_float2(p.z, -p.w);
            }
            v[n1] = make_float2(a.x - b.y, a.y + b.x);   // a + i*b
        }
        fft64<1>(v, twf, mask, j);     // v[k2] = row_a + i*row_b at w=j+8*k2
        const float scl = 1.0f / 4096.0f;   // ortho fwd (1/64) * ortho inv (1/64)
        #pragma unroll
        for (int k2 = 0; k2 < 8; k2++){
            int w = j + 8 * k2;
            op[r2 * 64 + w]       = v[k2].x * scl;
            op[(r2 + 1) * 64 + w] = v[k2].y * scl;
        }
    }
}

// ---------------------------------------------------------------------------
extern "C" void kernel_launch(void* const* d_in, const int* in_sizes, int n_in,
                              void* d_out, int out_size){
    const float* x;
    const float* w;
    if (in_sizes[0] == BB * CC * HH * WW){
        x = (const float*)d_in[0];
        w = (const float*)d_in[1];
    } else {
        x = (const float*)d_in[1];
        w = (const float*)d_in[0];
    }
    prep_weight_kernel<<<(CC * WG_ELEMS + 255) / 256, 256>>>(w);
    sgn_kernel<<<PLANES, 256>>>(x, (float*)d_out);
}